// round 7
// baseline (speedup 1.0000x reference)
#include <cuda_runtime.h>
#include <cuda_bf16.h>

// SpatialBlock: x[16,256,128,128] fp32
//   max_c(x), mean_c(x) -> conv7x7 (2->1, SAME zero pad) + bias -> hsigmoid -> x * gate
//
// R7: reduce 4-way channel split (256 thr/block: 64 px4 x 4 channel quarters,
//     shared tree combine) -> ~55 warps/SM, matching the residency at which
//     gate_mul sustains 6.3 TB/s. Warp-scaling evidence: 13.8w=4.7, 27.7w=5.16 TB/s.
//     Gate_mul at its mixed-stream ceiling; identical to R5/R6.

#define Bn 16
#define Cn 256
#define Hn 128
#define Wn 128
#define HWn (Hn * Wn)

__device__ float g_max[Bn * HWn];
__device__ float g_avg[Bn * HWn];

#define RPX 64   // float4 pixels per reduce block

__global__ void __launch_bounds__(256)
reduce_kernel(const float* __restrict__ x) {
    __shared__ __align__(16) float4 smx[4][RPX];
    __shared__ __align__(16) float4 ssm[4][RPX];

    int px = threadIdx.x & 63;            // 0..63: float4 pixel within block
    int q  = threadIdx.x >> 6;            // 0..3 : channel quarter

    int t  = blockIdx.x * RPX + px;       // global float4-pixel id
    int b  = t / (HWn / 4);
    int p4 = t - b * (HWn / 4);

    const float4* xb = reinterpret_cast<const float4*>(x) +
                       (size_t)b * Cn * (HWn / 4) +
                       (size_t)q * 64 * (HWn / 4) + p4;

    float4 v = __ldcs(xb);
    float4 mx = v;
    float4 sm = v;

#pragma unroll 16
    for (int c = 1; c < 64; c++) {
        float4 u = __ldcs(xb + (size_t)c * (HWn / 4));
        mx.x = fmaxf(mx.x, u.x); mx.y = fmaxf(mx.y, u.y);
        mx.z = fmaxf(mx.z, u.z); mx.w = fmaxf(mx.w, u.w);
        sm.x += u.x; sm.y += u.y; sm.z += u.z; sm.w += u.w;
    }

    smx[q][px] = mx;
    ssm[q][px] = sm;
    __syncthreads();

    if (threadIdx.x < RPX) {
        float4 m0 = smx[0][px], m1 = smx[1][px];
        float4 m2 = smx[2][px], m3 = smx[3][px];
        float4 s0 = ssm[0][px], s1 = ssm[1][px];
        float4 s2 = ssm[2][px], s3 = ssm[3][px];
        float4 mo, so;
        mo.x = fmaxf(fmaxf(m0.x, m1.x), fmaxf(m2.x, m3.x));
        mo.y = fmaxf(fmaxf(m0.y, m1.y), fmaxf(m2.y, m3.y));
        mo.z = fmaxf(fmaxf(m0.z, m1.z), fmaxf(m2.z, m3.z));
        mo.w = fmaxf(fmaxf(m0.w, m1.w), fmaxf(m2.w, m3.w));
        const float inv = 1.0f / (float)Cn;
        so.x = ((s0.x + s1.x) + (s2.x + s3.x)) * inv;
        so.y = ((s0.y + s1.y) + (s2.y + s3.y)) * inv;
        so.z = ((s0.z + s1.z) + (s2.z + s3.z)) * inv;
        so.w = ((s0.w + s1.w) + (s2.w + s3.w)) * inv;

        reinterpret_cast<float4*>(g_max)[(size_t)b * (HWn / 4) + p4] = mo;
        reinterpret_cast<float4*>(g_avg)[(size_t)b * (HWn / 4) + p4] = so;
    }
}

#define TW 32   // tile width  (pixels) -- 128B rows, full-line warp requests
#define TH 8    // tile height (pixels) -- 1024 blocks for wave balance

__global__ void __launch_bounds__(256)
gate_mul_kernel(const float* __restrict__ x,
                const float* __restrict__ cw,   // [1,2,7,7] = 98 floats
                const float* __restrict__ cb,   // [1]
                float* __restrict__ out) {
    __shared__ float sw[98];
    __shared__ float sbias;
    __shared__ __align__(16) float smax[TH + 6][TW + 6];
    __shared__ __align__(16) float savg[TH + 6][TW + 6];
    __shared__ __align__(16) float sgate[TH][TW];

    int tid = threadIdx.x;                        // 0..255
    if (tid < 98) sw[tid] = cw[tid];
    if (tid == 98) sbias = cb[0];

    int b  = blockIdx.z;
    int h0 = blockIdx.y * TH;
    int w0 = blockIdx.x * TW;

    const float* bmax = g_max + b * HWn;
    const float* bavg = g_avg + b * HWn;

    // Cooperative halo load (zero padding == conv SAME zero-pad). 14x38=532.
    for (int i = tid; i < (TH + 6) * (TW + 6); i += 256) {
        int r  = i / (TW + 6);
        int cc = i - r * (TW + 6);
        int hh = h0 + r - 3;
        int ww = w0 + cc - 3;
        float vm = 0.0f, va = 0.0f;
        if ((unsigned)hh < (unsigned)Hn && (unsigned)ww < (unsigned)Wn) {
            int gi = hh * Wn + ww;
            vm = bmax[gi];
            va = bavg[gi];
        }
        smax[r][cc] = vm;
        savg[r][cc] = va;
    }
    __syncthreads();

    // Conv + hsigmoid: 256 threads, one pixel each of the 32x8 tile
    {
        int r  = tid >> 5;         // 0..7
        int cp = tid & 31;         // 0..31
        float a0 = sbias;
#pragma unroll
        for (int ky = 0; ky < 7; ky++) {
#pragma unroll
            for (int kx = 0; kx < 7; kx++) {
                a0 += sw[ky * 7 + kx]      * smax[r + ky][cp + kx]
                    + sw[49 + ky * 7 + kx] * savg[r + ky][cp + kx];
            }
        }
        sgate[r][cp] = __saturatef((a0 + 3.0f) * (1.0f / 6.0f));
    }
    __syncthreads();

    // Broadcast multiply: thread = (channel-quarter, px4). 64 px4 in tile,
    // 4 quarters x 64 channels. Warp = 4 rows x 8 float4 = 128B/row.
    int px4 = tid & 63;            // 0..63
    int cq  = tid >> 6;            // 0..3
    int rr  = px4 >> 3;            // tile row 0..7
    int cc4 = px4 & 7;             // float4 col 0..7

    float4 g = *reinterpret_cast<const float4*>(&sgate[rr][cc4 * 4]);

    const size_t plane4 = HWn / 4;
    int prow4 = ((h0 + rr) * Wn + w0 + cc4 * 4) >> 2;
    const float4* xin = reinterpret_cast<const float4*>(x) +
                        (size_t)b * Cn * plane4 + (size_t)cq * 64 * plane4 + prow4;
    float4* xout = reinterpret_cast<float4*>(out) +
                   (size_t)b * Cn * plane4 + (size_t)cq * 64 * plane4 + prow4;

#pragma unroll 8
    for (int c = 0; c < 64; c++) {
        float4 v = __ldcs(xin + (size_t)c * plane4);
        v.x *= g.x; v.y *= g.y; v.z *= g.z; v.w *= g.w;
        __stcs(xout + (size_t)c * plane4, v);
    }
}

extern "C" void kernel_launch(void* const* d_in, const int* in_sizes, int n_in,
                              void* d_out, int out_size) {
    const float* x  = (const float*)d_in[0];
    const float* cw = (const float*)d_in[1];
    const float* cb = (const float*)d_in[2];
    float* out = (float*)d_out;

    // 1024 blocks x 256 threads (64 px4 x 4 channel quarters each)
    reduce_kernel<<<(Bn * HWn / 4) / RPX, 256>>>(x);

    // grid (4, 16, 16) = 1024 blocks x 256 threads
    gate_mul_kernel<<<dim3(Wn / TW, Hn / TH, Bn), 256>>>(x, cw, cb, out);
}

// round 8
// speedup vs baseline: 1.0473x; 1.0473x over previous
#include <cuda_runtime.h>
#include <cuda_bf16.h>

// SpatialBlock: x[16,256,128,128] fp32
//   max_c(x), mean_c(x) -> conv7x7 (2->1, SAME zero pad) + bias -> hsigmoid -> x * gate
//
// R8: reduce reverted to R6 (2-way split, 128 thr, 1024 blocks = measured-best
//     27.7 warps/SM; 4-way/55w regressed -> cross-CTA L1tex queue contention).
//     Unroll 16 -> 8 to halve MLP_p1 (front-batched LDG depth), cutting the
//     spr_max queue-contention tail. Gate_mul at its ceiling; unchanged.

#define Bn 16
#define Cn 256
#define Hn 128
#define Wn 128
#define HWn (Hn * Wn)

__device__ float g_max[Bn * HWn];
__device__ float g_avg[Bn * HWn];

#define RPX 64   // float4 pixels per reduce block

__global__ void __launch_bounds__(128)
reduce_kernel(const float* __restrict__ x) {
    __shared__ __align__(16) float4 smx[2][RPX];
    __shared__ __align__(16) float4 ssm[2][RPX];

    int px   = threadIdx.x & 63;          // 0..63: float4 pixel within block
    int half = threadIdx.x >> 6;          // 0 or 1: channel half

    int t  = blockIdx.x * RPX + px;       // global float4-pixel id
    int b  = t / (HWn / 4);
    int p4 = t - b * (HWn / 4);

    const float4* xb = reinterpret_cast<const float4*>(x) +
                       (size_t)b * Cn * (HWn / 4) +
                       (size_t)half * 128 * (HWn / 4) + p4;

    float4 v = __ldcs(xb);
    float4 mx = v;
    float4 sm = v;

#pragma unroll 8
    for (int c = 1; c < 128; c++) {
        float4 u = __ldcs(xb + (size_t)c * (HWn / 4));
        mx.x = fmaxf(mx.x, u.x); mx.y = fmaxf(mx.y, u.y);
        mx.z = fmaxf(mx.z, u.z); mx.w = fmaxf(mx.w, u.w);
        sm.x += u.x; sm.y += u.y; sm.z += u.z; sm.w += u.w;
    }

    smx[half][px] = mx;
    ssm[half][px] = sm;
    __syncthreads();

    if (threadIdx.x < RPX) {
        float4 m0 = smx[0][px], m1 = smx[1][px];
        float4 s0 = ssm[0][px], s1 = ssm[1][px];
        float4 mo, so;
        mo.x = fmaxf(m0.x, m1.x); mo.y = fmaxf(m0.y, m1.y);
        mo.z = fmaxf(m0.z, m1.z); mo.w = fmaxf(m0.w, m1.w);
        const float inv = 1.0f / (float)Cn;
        so.x = (s0.x + s1.x) * inv; so.y = (s0.y + s1.y) * inv;
        so.z = (s0.z + s1.z) * inv; so.w = (s0.w + s1.w) * inv;

        reinterpret_cast<float4*>(g_max)[(size_t)b * (HWn / 4) + p4] = mo;
        reinterpret_cast<float4*>(g_avg)[(size_t)b * (HWn / 4) + p4] = so;
    }
}

#define TW 32   // tile width  (pixels) -- 128B rows, full-line warp requests
#define TH 8    // tile height (pixels) -- 1024 blocks for wave balance

__global__ void __launch_bounds__(256)
gate_mul_kernel(const float* __restrict__ x,
                const float* __restrict__ cw,   // [1,2,7,7] = 98 floats
                const float* __restrict__ cb,   // [1]
                float* __restrict__ out) {
    __shared__ float sw[98];
    __shared__ float sbias;
    __shared__ __align__(16) float smax[TH + 6][TW + 6];
    __shared__ __align__(16) float savg[TH + 6][TW + 6];
    __shared__ __align__(16) float sgate[TH][TW];

    int tid = threadIdx.x;                        // 0..255
    if (tid < 98) sw[tid] = cw[tid];
    if (tid == 98) sbias = cb[0];

    int b  = blockIdx.z;
    int h0 = blockIdx.y * TH;
    int w0 = blockIdx.x * TW;

    const float* bmax = g_max + b * HWn;
    const float* bavg = g_avg + b * HWn;

    // Cooperative halo load (zero padding == conv SAME zero-pad). 14x38=532.
    for (int i = tid; i < (TH + 6) * (TW + 6); i += 256) {
        int r  = i / (TW + 6);
        int cc = i - r * (TW + 6);
        int hh = h0 + r - 3;
        int ww = w0 + cc - 3;
        float vm = 0.0f, va = 0.0f;
        if ((unsigned)hh < (unsigned)Hn && (unsigned)ww < (unsigned)Wn) {
            int gi = hh * Wn + ww;
            vm = bmax[gi];
            va = bavg[gi];
        }
        smax[r][cc] = vm;
        savg[r][cc] = va;
    }
    __syncthreads();

    // Conv + hsigmoid: 256 threads, one pixel each of the 32x8 tile
    {
        int r  = tid >> 5;         // 0..7
        int cp = tid & 31;         // 0..31
        float a0 = sbias;
#pragma unroll
        for (int ky = 0; ky < 7; ky++) {
#pragma unroll
            for (int kx = 0; kx < 7; kx++) {
                a0 += sw[ky * 7 + kx]      * smax[r + ky][cp + kx]
                    + sw[49 + ky * 7 + kx] * savg[r + ky][cp + kx];
            }
        }
        sgate[r][cp] = __saturatef((a0 + 3.0f) * (1.0f / 6.0f));
    }
    __syncthreads();

    // Broadcast multiply: thread = (channel-quarter, px4). 64 px4 in tile,
    // 4 quarters x 64 channels. Warp = 4 rows x 8 float4 = 128B/row.
    int px4 = tid & 63;            // 0..63
    int cq  = tid >> 6;            // 0..3
    int rr  = px4 >> 3;            // tile row 0..7
    int cc4 = px4 & 7;             // float4 col 0..7

    float4 g = *reinterpret_cast<const float4*>(&sgate[rr][cc4 * 4]);

    const size_t plane4 = HWn / 4;
    int prow4 = ((h0 + rr) * Wn + w0 + cc4 * 4) >> 2;
    const float4* xin = reinterpret_cast<const float4*>(x) +
                        (size_t)b * Cn * plane4 + (size_t)cq * 64 * plane4 + prow4;
    float4* xout = reinterpret_cast<float4*>(out) +
                   (size_t)b * Cn * plane4 + (size_t)cq * 64 * plane4 + prow4;

#pragma unroll 8
    for (int c = 0; c < 64; c++) {
        float4 v = __ldcs(xin + (size_t)c * plane4);
        v.x *= g.x; v.y *= g.y; v.z *= g.z; v.w *= g.w;
        __stcs(xout + (size_t)c * plane4, v);
    }
}

extern "C" void kernel_launch(void* const* d_in, const int* in_sizes, int n_in,
                              void* d_out, int out_size) {
    const float* x  = (const float*)d_in[0];
    const float* cw = (const float*)d_in[1];
    const float* cb = (const float*)d_in[2];
    float* out = (float*)d_out;

    // 1024 blocks x 128 threads (64 px4 x 2 channel halves each)
    reduce_kernel<<<(Bn * HWn / 4) / RPX, 128>>>(x);

    // grid (4, 16, 16) = 1024 blocks x 256 threads
    gate_mul_kernel<<<dim3(Wn / TW, Hn / TH, Bn), 256>>>(x, cw, cb, out);
}

// round 9
// speedup vs baseline: 1.0684x; 1.0201x over previous
#include <cuda_runtime.h>
#include <cuda_bf16.h>
#include <cstdint>

// SpatialBlock: x[16,256,128,128] fp32
//   max_c(x), mean_c(x) -> conv7x7 (2->1, SAME zero pad) + bias -> hsigmoid -> x * gate
//
// R9: reduce rebuilt as a cp.async.bulk (TMA-path) producer/consumer pipeline.
//     Per-warp LDG streams plateaued at 5.2 TB/s (13.8w=4.7, 27.7w=5.16,
//     55w=4.64 TB/s -- L1tex queue contention). Bulk async copies bypass the
//     per-warp queue; latency covered by a 3-stage smem ring, not warp count.
//     Gate_mul at its mixed-stream ceiling (6.24 TB/s); unchanged from R5.

#define Bn 16
#define Cn 256
#define Hn 128
#define Wn 128
#define HWn (Hn * Wn)
#define PLANE4 (HWn / 4)      // 4096 float4 per plane

__device__ float g_max[Bn * HWn];
__device__ float g_avg[Bn * HWn];

#define RPX 64                 // float4 pixels per block (1024 B per channel)
#define CPS 8                  // channels per pipeline stage
#define NSTG 3                 // ring stages (24 KB)
#define NSTEPS (Cn / CPS)      // 32 stages total

__device__ __forceinline__ uint32_t smem_u32(const void* p) {
    uint32_t a;
    asm("{ .reg .u64 t; cvta.to.shared.u64 t, %1; cvt.u32.u64 %0, t; }"
        : "=r"(a) : "l"(p));
    return a;
}

__global__ void __launch_bounds__(160)
reduce_kernel(const float* __restrict__ x) {
    __shared__ __align__(16) float4 buf[NSTG][CPS][RPX];   // 24 KB
    __shared__ __align__(16) float4 smx[2][RPX];
    __shared__ __align__(16) float4 ssm[2][RPX];
    __shared__ uint64_t mb_full[NSTG];
    __shared__ uint64_t mb_empty[NSTG];

    int tid = threadIdx.x;
    int b   = blockIdx.x / (PLANE4 / RPX);           // 64 blocks per plane
    int p0  = (blockIdx.x % (PLANE4 / RPX)) * RPX;   // first float4 pixel

    if (tid == 0) {
        for (int s = 0; s < NSTG; s++) {
            asm volatile("mbarrier.init.shared.b64 [%0], %1;"
                         :: "r"(smem_u32(&mb_full[s])), "r"(1) : "memory");
            asm volatile("mbarrier.init.shared.b64 [%0], %1;"
                         :: "r"(smem_u32(&mb_empty[s])), "r"(128) : "memory");
        }
        asm volatile("fence.proxy.async.shared::cta;" ::: "memory");
    }
    __syncthreads();

    if (tid >= 128) {
        // ---------- producer warp (one elected thread) ----------
        if (tid == 128) {
            const float4* src0 = reinterpret_cast<const float4*>(x) +
                                 (size_t)b * Cn * PLANE4 + p0;
            int slot = 0, ph = 1;          // phase trick: first empty-wait passes
            for (int s = 0; s < NSTEPS; s++) {
                uint32_t e = smem_u32(&mb_empty[slot]);
                asm volatile(
                    "{\n\t.reg .pred P;\n\t"
                    "PW%=:\n\t"
                    "mbarrier.try_wait.parity.relaxed.cta.shared::cta.b64 P, [%0], %1;\n\t"
                    "@!P bra PW%=;\n\t}"
                    :: "r"(e), "r"(ph) : "memory");

                uint32_t f = smem_u32(&mb_full[slot]);
                asm volatile("mbarrier.arrive.expect_tx.shared.b64 _, [%0], %1;"
                             :: "r"(f), "r"(CPS * RPX * 16) : "memory");
#pragma unroll
                for (int c = 0; c < CPS; c++) {
                    const float4* src = src0 + (size_t)(s * CPS + c) * PLANE4;
                    uint32_t d = smem_u32(&buf[slot][c][0]);
                    asm volatile(
                        "cp.async.bulk.shared::cta.global.mbarrier::complete_tx::bytes "
                        "[%0], [%1], %2, [%3];"
                        :: "r"(d), "l"(src), "r"(RPX * 16), "r"(f) : "memory");
                }
                if (++slot == NSTG) { slot = 0; ph ^= 1; }
            }
        }
    } else {
        // ---------- 128 consumers: (px, channel-parity h) ----------
        int px = tid & 63;
        int h  = tid >> 6;

        float4 mx = make_float4(-3.402823466e38f, -3.402823466e38f,
                                -3.402823466e38f, -3.402823466e38f);
        float4 sm = make_float4(0.f, 0.f, 0.f, 0.f);

        int slot = 0, ph = 0;
        for (int s = 0; s < NSTEPS; s++) {
            uint32_t f = smem_u32(&mb_full[slot]);
            asm volatile(
                "{\n\t.reg .pred P;\n\t"
                "CW%=:\n\t"
                "mbarrier.try_wait.parity.acquire.cta.shared::cta.b64 P, [%0], %1;\n\t"
                "@!P bra CW%=;\n\t}"
                :: "r"(f), "r"(ph) : "memory");

#pragma unroll
            for (int cl = 0; cl < CPS / 2; cl++) {
                float4 u = buf[slot][2 * cl + h][px];
                mx.x = fmaxf(mx.x, u.x); mx.y = fmaxf(mx.y, u.y);
                mx.z = fmaxf(mx.z, u.z); mx.w = fmaxf(mx.w, u.w);
                sm.x += u.x; sm.y += u.y; sm.z += u.z; sm.w += u.w;
            }

            asm volatile("mbarrier.arrive.shared.b64 _, [%0];"
                         :: "r"(smem_u32(&mb_empty[slot])) : "memory");
            if (++slot == NSTG) { slot = 0; ph ^= 1; }
        }
        smx[h][px] = mx;
        ssm[h][px] = sm;
    }
    __syncthreads();

    if (tid < RPX) {
        int px = tid;
        float4 m0 = smx[0][px], m1 = smx[1][px];
        float4 s0 = ssm[0][px], s1 = ssm[1][px];
        float4 mo, so;
        mo.x = fmaxf(m0.x, m1.x); mo.y = fmaxf(m0.y, m1.y);
        mo.z = fmaxf(m0.z, m1.z); mo.w = fmaxf(m0.w, m1.w);
        const float inv = 1.0f / (float)Cn;
        so.x = (s0.x + s1.x) * inv; so.y = (s0.y + s1.y) * inv;
        so.z = (s0.z + s1.z) * inv; so.w = (s0.w + s1.w) * inv;

        reinterpret_cast<float4*>(g_max)[(size_t)b * PLANE4 + p0 + px] = mo;
        reinterpret_cast<float4*>(g_avg)[(size_t)b * PLANE4 + p0 + px] = so;
    }
}

#define TW 32   // tile width  (pixels) -- 128B rows, full-line warp requests
#define TH 8    // tile height (pixels) -- 1024 blocks for wave balance

__global__ void __launch_bounds__(256)
gate_mul_kernel(const float* __restrict__ x,
                const float* __restrict__ cw,   // [1,2,7,7] = 98 floats
                const float* __restrict__ cb,   // [1]
                float* __restrict__ out) {
    __shared__ float sw[98];
    __shared__ float sbias;
    __shared__ __align__(16) float smax[TH + 6][TW + 6];
    __shared__ __align__(16) float savg[TH + 6][TW + 6];
    __shared__ __align__(16) float sgate[TH][TW];

    int tid = threadIdx.x;                        // 0..255
    if (tid < 98) sw[tid] = cw[tid];
    if (tid == 98) sbias = cb[0];

    int b  = blockIdx.z;
    int h0 = blockIdx.y * TH;
    int w0 = blockIdx.x * TW;

    const float* bmax = g_max + b * HWn;
    const float* bavg = g_avg + b * HWn;

    // Cooperative halo load (zero padding == conv SAME zero-pad). 14x38=532.
    for (int i = tid; i < (TH + 6) * (TW + 6); i += 256) {
        int r  = i / (TW + 6);
        int cc = i - r * (TW + 6);
        int hh = h0 + r - 3;
        int ww = w0 + cc - 3;
        float vm = 0.0f, va = 0.0f;
        if ((unsigned)hh < (unsigned)Hn && (unsigned)ww < (unsigned)Wn) {
            int gi = hh * Wn + ww;
            vm = bmax[gi];
            va = bavg[gi];
        }
        smax[r][cc] = vm;
        savg[r][cc] = va;
    }
    __syncthreads();

    // Conv + hsigmoid: 256 threads, one pixel each of the 32x8 tile
    {
        int r  = tid >> 5;         // 0..7
        int cp = tid & 31;         // 0..31
        float a0 = sbias;
#pragma unroll
        for (int ky = 0; ky < 7; ky++) {
#pragma unroll
            for (int kx = 0; kx < 7; kx++) {
                a0 += sw[ky * 7 + kx]      * smax[r + ky][cp + kx]
                    + sw[49 + ky * 7 + kx] * savg[r + ky][cp + kx];
            }
        }
        sgate[r][cp] = __saturatef((a0 + 3.0f) * (1.0f / 6.0f));
    }
    __syncthreads();

    // Broadcast multiply: thread = (channel-quarter, px4). 64 px4 in tile,
    // 4 quarters x 64 channels. Warp = 4 rows x 8 float4 = 128B/row.
    int px4 = tid & 63;            // 0..63
    int cq  = tid >> 6;            // 0..3
    int rr  = px4 >> 3;            // tile row 0..7
    int cc4 = px4 & 7;             // float4 col 0..7

    float4 g = *reinterpret_cast<const float4*>(&sgate[rr][cc4 * 4]);

    const size_t plane4 = HWn / 4;
    int prow4 = ((h0 + rr) * Wn + w0 + cc4 * 4) >> 2;
    const float4* xin = reinterpret_cast<const float4*>(x) +
                        (size_t)b * Cn * plane4 + (size_t)cq * 64 * plane4 + prow4;
    float4* xout = reinterpret_cast<float4*>(out) +
                   (size_t)b * Cn * plane4 + (size_t)cq * 64 * plane4 + prow4;

#pragma unroll 8
    for (int c = 0; c < 64; c++) {
        float4 v = __ldcs(xin + (size_t)c * plane4);
        v.x *= g.x; v.y *= g.y; v.z *= g.z; v.w *= g.w;
        __stcs(xout + (size_t)c * plane4, v);
    }
}

extern "C" void kernel_launch(void* const* d_in, const int* in_sizes, int n_in,
                              void* d_out, int out_size) {
    const float* x  = (const float*)d_in[0];
    const float* cw = (const float*)d_in[1];
    const float* cb = (const float*)d_in[2];
    float* out = (float*)d_out;

    // 1024 blocks x 160 threads (1 producer warp + 128 consumers)
    reduce_kernel<<<(Bn * PLANE4) / RPX, 160>>>(x);

    // grid (4, 16, 16) = 1024 blocks x 256 threads
    gate_mul_kernel<<<dim3(Wn / TW, Hn / TH, Bn), 256>>>(x, cw, cb, out);
}